// round 1
// baseline (speedup 1.0000x reference)
#include <cuda_runtime.h>

// Problem constants
#define B_TOT    4096
#define T_LEN    512
#define D_IN     7
#define H        64
#define G        256      // 4*H gate width
#define OUT_D    4
#define BTILE    32       // batch rows per CTA
#define NTHREADS 512      // 16 warps: warp = 4 hidden units, lane = batch row

__device__ __forceinline__ float sigf(float x) {
    // 1/(1+exp(-x)) via EX2 + MUFU.RCP
    return __fdividef(1.0f, 1.0f + __expf(-x));
}
__device__ __forceinline__ float tanhf_fast(float x) {
    // tanh(x) = 2*sigmoid(2x) - 1 ; abs error ~1e-7, safe near 0 and saturates correctly
    return __fdividef(2.0f, 1.0f + __expf(-2.0f * x)) - 1.0f;
}

__global__ __launch_bounds__(NTHREADS, 1)
void lstm_fused_kernel(const float* __restrict__ x,
                       const float* __restrict__ W_ih0, const float* __restrict__ W_hh0,
                       const float* __restrict__ b_ih0, const float* __restrict__ b_hh0,
                       const float* __restrict__ W_ih1, const float* __restrict__ W_hh1,
                       const float* __restrict__ b_ih1, const float* __restrict__ b_hh1,
                       const float* __restrict__ W_fc,  const float* __restrict__ b_fc,
                       float* __restrict__ out)
{
    extern __shared__ float smem[];
    float* s_wih0 = smem;                    // [7][256]   transposed: [d][g]
    float* s_whh0 = s_wih0 + D_IN * G;       // [64][256]  transposed: [k][g]
    float* s_wih1 = s_whh0 + H * G;          // [64][256]
    float* s_whh1 = s_wih1 + H * G;          // [64][256]
    float* s_b0   = s_whh1 + H * G;          // [256] combined b_ih0+b_hh0
    float* s_b1   = s_b0 + G;                // [256]
    float* s_wfc  = s_b1 + G;                // [4][64]
    float* s_bfc  = s_wfc + OUT_D * H;       // [4] (+pad)
    float* s_h0   = s_bfc + 8;               // [64][32]  h layer0, [k][b]
    float* s_h1   = s_h0 + H * BTILE;        // [64][32]  h layer1

    const int tid  = threadIdx.x;
    const int lane = tid & 31;               // batch row within tile
    const int w    = tid >> 5;               // warp id 0..15
    const int u0   = w * 4;                  // this warp's 4 hidden units: u0..u0+3

    // ---- stage weights into smem (transposed so gate dim is contiguous) ----
    for (int idx = tid; idx < D_IN * G; idx += NTHREADS) {
        int d = idx >> 8, g = idx & 255;
        s_wih0[idx] = W_ih0[g * D_IN + d];
    }
    for (int idx = tid; idx < H * G; idx += NTHREADS) {
        int k = idx >> 8, g = idx & 255;
        s_whh0[idx] = W_hh0[g * H + k];
        s_wih1[idx] = W_ih1[g * H + k];
        s_whh1[idx] = W_hh1[g * H + k];
    }
    for (int g = tid; g < G; g += NTHREADS) {
        s_b0[g] = b_ih0[g] + b_hh0[g];
        s_b1[g] = b_ih1[g] + b_hh1[g];
    }
    for (int i = tid; i < OUT_D * H; i += NTHREADS) s_wfc[i] = W_fc[i];
    if (tid < OUT_D) s_bfc[tid] = b_fc[tid];
    for (int i = tid; i < H * BTILE; i += NTHREADS) { s_h0[i] = 0.0f; s_h1[i] = 0.0f; }
    __syncthreads();

    float c0r[4] = {0.f, 0.f, 0.f, 0.f};
    float c1r[4] = {0.f, 0.f, 0.f, 0.f};

    const int b = blockIdx.x * BTILE + lane;
    const float* xb = x + (size_t)b * T_LEN * D_IN;

    for (int t = 0; t < T_LEN; t++) {
        // per-lane input vector for this step
        float xr[D_IN];
        #pragma unroll
        for (int d = 0; d < D_IN; d++) xr[d] = __ldg(xb + t * D_IN + d);

        // gate accumulators: [blk i,f,g,o][unit j]
        float a0[16], a1[16];
        #pragma unroll
        for (int blk = 0; blk < 4; blk++) {
            float4 bv0 = *(const float4*)&s_b0[blk * 64 + u0];
            float4 bv1 = *(const float4*)&s_b1[blk * 64 + u0];
            a0[blk*4+0] = bv0.x; a0[blk*4+1] = bv0.y; a0[blk*4+2] = bv0.z; a0[blk*4+3] = bv0.w;
            a1[blk*4+0] = bv1.x; a1[blk*4+1] = bv1.y; a1[blk*4+2] = bv1.z; a1[blk*4+3] = bv1.w;
        }

        // ---- phase 1: x @ W_ih0^T, h0 @ W_hh0^T, h1 @ W_hh1^T ----
        #pragma unroll
        for (int d = 0; d < D_IN; d++) {
            float xv = xr[d];
            #pragma unroll
            for (int blk = 0; blk < 4; blk++) {
                float4 wv = *(const float4*)&s_wih0[d * G + blk * 64 + u0];
                a0[blk*4+0] += xv * wv.x;
                a0[blk*4+1] += xv * wv.y;
                a0[blk*4+2] += xv * wv.z;
                a0[blk*4+3] += xv * wv.w;
            }
        }
        #pragma unroll 4
        for (int k = 0; k < H; k++) {
            float h0v = s_h0[k * BTILE + lane];
            float h1v = s_h1[k * BTILE + lane];
            #pragma unroll
            for (int blk = 0; blk < 4; blk++) {
                float4 w0 = *(const float4*)&s_whh0[k * G + blk * 64 + u0];
                a0[blk*4+0] += h0v * w0.x;
                a0[blk*4+1] += h0v * w0.y;
                a0[blk*4+2] += h0v * w0.z;
                a0[blk*4+3] += h0v * w0.w;
                float4 w1 = *(const float4*)&s_whh1[k * G + blk * 64 + u0];
                a1[blk*4+0] += h1v * w1.x;
                a1[blk*4+1] += h1v * w1.y;
                a1[blk*4+2] += h1v * w1.z;
                a1[blk*4+3] += h1v * w1.w;
            }
        }

        // layer-0 cell update (c in registers)
        float h0new[4];
        #pragma unroll
        for (int j = 0; j < 4; j++) {
            float ig = sigf(a0[0*4 + j]);
            float fg = sigf(a0[1*4 + j]);
            float gg = tanhf_fast(a0[2*4 + j]);
            float og = sigf(a0[3*4 + j]);
            c0r[j] = fg * c0r[j] + ig * gg;
            h0new[j] = og * tanhf_fast(c0r[j]);
        }

        __syncthreads();   // all warps finished reading s_h0 / s_h1 for this step
        #pragma unroll
        for (int j = 0; j < 4; j++) s_h0[(u0 + j) * BTILE + lane] = h0new[j];
        __syncthreads();   // new h0 visible to all warps

        // ---- phase 2: h0(new) @ W_ih1^T ----
        #pragma unroll 4
        for (int k = 0; k < H; k++) {
            float hv = s_h0[k * BTILE + lane];
            #pragma unroll
            for (int blk = 0; blk < 4; blk++) {
                float4 wv = *(const float4*)&s_wih1[k * G + blk * 64 + u0];
                a1[blk*4+0] += hv * wv.x;
                a1[blk*4+1] += hv * wv.y;
                a1[blk*4+2] += hv * wv.z;
                a1[blk*4+3] += hv * wv.w;
            }
        }

        // layer-1 cell update; write h1 (phase 2 never reads s_h1, so safe)
        #pragma unroll
        for (int j = 0; j < 4; j++) {
            float ig = sigf(a1[0*4 + j]);
            float fg = sigf(a1[1*4 + j]);
            float gg = tanhf_fast(a1[2*4 + j]);
            float og = sigf(a1[3*4 + j]);
            c1r[j] = fg * c1r[j] + ig * gg;
            s_h1[(u0 + j) * BTILE + lane] = og * tanhf_fast(c1r[j]);
        }
        __syncthreads();   // h1 complete before next step's phase 1 reads it
    }

    // ---- epilogue: out[b] = h1_last[b] @ W_fc^T + b_fc (warp 0 only) ----
    if (tid < 32) {
        float acc[OUT_D];
        #pragma unroll
        for (int o = 0; o < OUT_D; o++) acc[o] = s_bfc[o];
        #pragma unroll 8
        for (int k = 0; k < H; k++) {
            float hv = s_h1[k * BTILE + lane];
            #pragma unroll
            for (int o = 0; o < OUT_D; o++) acc[o] += hv * s_wfc[o * H + k];
        }
        #pragma unroll
        for (int o = 0; o < OUT_D; o++)
            out[(size_t)b * OUT_D + o] = acc[o];
    }
}

extern "C" void kernel_launch(void* const* d_in, const int* in_sizes, int n_in,
                              void* d_out, int out_size)
{
    const float* x     = (const float*)d_in[0];
    const float* W_ih0 = (const float*)d_in[1];
    const float* W_hh0 = (const float*)d_in[2];
    const float* b_ih0 = (const float*)d_in[3];
    const float* b_hh0 = (const float*)d_in[4];
    const float* W_ih1 = (const float*)d_in[5];
    const float* W_hh1 = (const float*)d_in[6];
    const float* b_ih1 = (const float*)d_in[7];
    const float* b_hh1 = (const float*)d_in[8];
    const float* W_fc  = (const float*)d_in[9];
    const float* b_fc  = (const float*)d_in[10];
    float* out = (float*)d_out;

    const size_t smem_floats = (size_t)D_IN * G + 3 * (size_t)H * G + 2 * G
                             + OUT_D * H + 8 + 2 * (size_t)H * BTILE;
    const size_t smem_bytes = smem_floats * sizeof(float);   // 223,264 B

    cudaFuncSetAttribute(lstm_fused_kernel,
                         cudaFuncAttributeMaxDynamicSharedMemorySize,
                         (int)smem_bytes);

    lstm_fused_kernel<<<B_TOT / BTILE, NTHREADS, smem_bytes>>>(
        x, W_ih0, W_hh0, b_ih0, b_hh0,
        W_ih1, W_hh1, b_ih1, b_hh1, W_fc, b_fc, out);
}